// round 16
// baseline (speedup 1.0000x reference)
#include <cuda_runtime.h>
#include <cuda_bf16.h>

#define V_SZ 8
#define J_SZ 64
#define NTHREADS 256          // 8 warps; warp w owns view w
#define BPB 8                 // batch elements per block
#define T09 219.711923f       // 400^0.9
#define THRESH 400.0f
#define MAX_BLOCKS 8192

// Scratch (allocation-free rule: __device__ globals)
__device__ float g_part[MAX_BLOCKS];
__device__ unsigned g_ctr = 0;

__global__ void __launch_bounds__(NTHREADS) pl_kernel(
    const float* __restrict__ kgt,   // [B,J,3]
    const float* __restrict__ kpr,   // [B,J,3]
    const float* __restrict__ gR,    // [B,V,3,3]
    const float* __restrict__ gt,    // [B,V,3]
    const float* __restrict__ Km,    // [V,3,3]
    const float* __restrict__ cam,   // [B,V,3,4]
    float* __restrict__ out, int B, int nblocks)
{
    // Double-buffered staging
    __shared__ float4 s_kgt[2][J_SZ];            // padded (x,y,z,0)
    __shared__ float4 s_kpr[2][J_SZ];
    __shared__ __align__(16) float s_raw[2][192];        // R[72] | t[24] | cam[96]
    __shared__ __align__(16) float s_mats[2][V_SZ][24];  // per view: M[3][4] | Mc[3][4]
    __shared__ float s_K[72];
    __shared__ float s_wsum[NTHREADS / 32];
    __shared__ double s_d[NTHREADS / 32];
    __shared__ bool s_last;

    const int tid  = threadIdx.x;
    const int w    = tid >> 5;
    const int lane = tid & 31;
    const int b0   = blockIdx.x * BPB;

    if (tid < 72) s_K[tid] = Km[tid];

    // --- staging helpers (threads < 176 participate) ---
    auto ldg_stage = [&](int b, float4& v4) {
        if (tid < 64) {
            const float* p = kgt + (size_t)b * 192 + tid * 3;
            v4.x = p[0]; v4.y = p[1]; v4.z = p[2]; v4.w = 0.0f;
        } else if (tid < 128) {
            const float* p = kpr + (size_t)b * 192 + (tid - 64) * 3;
            v4.x = p[0]; v4.y = p[1]; v4.z = p[2]; v4.w = 0.0f;
        } else if (tid < 176) {
            const int i = tid - 128;
            if (i < 18)      v4 = reinterpret_cast<const float4*>(gR  + (size_t)b * 72)[i];
            else if (i < 24) v4 = reinterpret_cast<const float4*>(gt  + (size_t)b * 24)[i - 18];
            else             v4 = reinterpret_cast<const float4*>(cam + (size_t)b * 96)[i - 24];
        }
    };
    auto commit = [&](int buf, const float4& v4) {
        if (tid < 64)       s_kgt[buf][tid] = v4;
        else if (tid < 128) s_kpr[buf][tid - 64] = v4;
        else if (tid < 176) reinterpret_cast<float4*>(s_raw[buf])[tid - 128] = v4;
    };

    // ---- Prologue: stage batch b0 into buffer 0
    float4 v4 = make_float4(0.f, 0.f, 0.f, 0.f);
    if (b0 < B) { ldg_stage(b0, v4); commit(0, v4); }
    __syncthreads();                       // buf[0] raw + s_K visible

    float acc = 0.0f;

    #pragma unroll
    for (int bb = 0; bb < BPB; bb++) {
        const int cur = bb & 1, nxt = cur ^ 1;
        const int b = b0 + bb;
        const bool pf = (bb + 1 < BPB) && (b + 1 < B);
        const bool active = (b < B);

        // ---- Warp-local fusion: warp w computes its own view's M=K@[R|t], Mc=K@cam
        if (active && lane < 24) {
            const float* Kv = s_K + w * 9;
            float e0, e1, e2;
            if (lane < 12) {
                const int c = lane & 3;
                if (c < 3) { const float* Rv = s_raw[cur] + w * 9;      e0 = Rv[c]; e1 = Rv[3 + c]; e2 = Rv[6 + c]; }
                else       { const float* tv = s_raw[cur] + 72 + w * 3; e0 = tv[0]; e1 = tv[1];     e2 = tv[2]; }
                const int i = lane >> 2;
                s_mats[cur][w][lane] = Kv[i * 3 + 0] * e0 + Kv[i * 3 + 1] * e1 + Kv[i * 3 + 2] * e2;
            } else {
                const int e = lane - 12, i = e >> 2, c = e & 3;
                const float* Cv = s_raw[cur] + 96 + w * 12;
                s_mats[cur][w][lane] = Kv[i * 3 + 0] * Cv[c] + Kv[i * 3 + 1] * Cv[4 + c] + Kv[i * 3 + 2] * Cv[8 + c];
            }
        }

        // ---- Kick off prefetch of next batch (hidden under compute)
        if (pf) ldg_stage(b + 1, v4);

        __syncwarp();                      // s_mats[cur][w] ready (same-warp producer)

        if (active) {
            const float4* mm = reinterpret_cast<const float4*>(s_mats[cur][w]);
            const float4 m0 = mm[0], m1 = mm[1], m2 = mm[2];   // M rows
            const float4 c0 = mm[3], c1 = mm[4], c2 = mm[5];   // Mc rows

            #pragma unroll
            for (int jj = 0; jj < 2; jj++) {
                const int j = lane + jj * 32;
                const float4 X = s_kgt[cur][j];
                const float4 P = s_kpr[cur][j];

                const float x0 = m0.w + m0.x * X.x + m0.y * X.y + m0.z * X.z;
                const float x1 = m1.w + m1.x * X.x + m1.y * X.y + m1.z * X.z;
                const float x2 = m2.w + m2.x * X.x + m2.y * X.y + m2.z * X.z;

                const float y0 = c0.w + c0.x * P.x + c0.y * P.y + c0.z * P.z;
                const float y1 = c1.w + c1.x * P.x + c1.y * P.y + c1.z * P.z;
                const float y2 = c2.w + c2.x * P.x + c2.y * P.y + c2.z * P.z;

                // gx-px = (x0*y2 - y0*x2) / (x2*y2): one rcp serves both components
                const float r  = __fdividef(1.0f, x2 * y2);
                float dx = (x0 * y2 - y0 * x2) * r;
                float dy = (x1 * y2 - y1 * x2) * r;
                dx *= dx; dy *= dy;
                acc += (dx > THRESH) ? (__powf(dx, 0.1f) * T09) : dx;
                acc += (dy > THRESH) ? (__powf(dy, 0.1f) * T09) : dy;
            }
        }

        // ---- Commit prefetched data to the alternate buffer
        if (pf) commit(nxt, v4);
        __syncthreads();                   // buf[nxt] complete; buf[cur] fully consumed
    }

    // ---- Block reduction: one float per block
    #pragma unroll
    for (int o = 16; o > 0; o >>= 1)
        acc += __shfl_down_sync(0xFFFFFFFFu, acc, o);
    if (lane == 0) s_wsum[w] = acc;
    __syncthreads();
    if (tid < (NTHREADS / 32)) {
        float t = s_wsum[tid];
        #pragma unroll
        for (int o = (NTHREADS / 64); o > 0; o >>= 1)
            t += __shfl_down_sync(0xFFu, t, o);
        if (tid == 0) g_part[blockIdx.x] = t;
    }
    __threadfence();
    __syncthreads();

    // ---- Last block performs the final reduction (fixed order: deterministic)
    if (tid == 0) {
        unsigned c = atomicAdd(&g_ctr, 1);
        s_last = (c == gridDim.x - 1);
    }
    __syncthreads();
    if (s_last) {
        double dsum = 0.0;
        for (int i = tid; i < nblocks; i += NTHREADS)
            dsum += (double)__ldcg(&g_part[i]);
        #pragma unroll
        for (int o = 16; o > 0; o >>= 1)
            dsum += __shfl_down_sync(0xFFFFFFFFu, dsum, o);
        if (lane == 0) s_d[w] = dsum;
        __syncthreads();
        if (tid < (NTHREADS / 32)) {
            double t2 = s_d[tid];
            #pragma unroll
            for (int o = (NTHREADS / 64); o > 0; o >>= 1)
                t2 += __shfl_down_sync(0xFFu, t2, o);
            if (tid == 0) {
                *out = (float)(t2 / (2.0 * (double)B));
                g_ctr = 0;   // reset for next graph replay
            }
        }
    }
}

extern "C" void kernel_launch(void* const* d_in, const int* in_sizes, int n_in,
                              void* d_out, int out_size) {
    const float* kgt = (const float*)d_in[0];   // [B,J,3]
    const float* kpr = (const float*)d_in[1];   // [B,J,3]
    const float* gR  = (const float*)d_in[2];   // [B,V,3,3]
    const float* gt  = (const float*)d_in[3];   // [B,V,3]
    const float* Km  = (const float*)d_in[4];   // [V,3,3]
    const float* cam = (const float*)d_in[5];   // [B,V,3,4]
    float* out = (float*)d_out;

    const int B = in_sizes[0] / (J_SZ * 3);
    const int nblocks = (B + BPB - 1) / BPB;    // 2048 for B=16384

    pl_kernel<<<nblocks, NTHREADS>>>(kgt, kpr, gR, gt, Km, cam, out, B, nblocks);
}